// round 5
// baseline (speedup 1.0000x reference)
#include <cuda_runtime.h>
#include <cstdint>
#include <cstddef>

#define BD 128     // batch
#define TD 256     // seq len
#define HD 512     // hidden
#define G3 1536    // 3*H
#define LD 3       // layers
#define MD (BD*TD) // 32768 rows for input GEMM

// ---------------- scratch (static device allocations; no cudaMalloc) -------
__device__ float g_XP[(size_t)MD * G3];          // input projections
__device__ float g_X1[(size_t)MD * HD];          // layer0 seq out
__device__ float g_X2[(size_t)MD * HD];          // layer1 seq out
__device__ float g_WuT[(size_t)LD * G3 * HD];    // transposed recurrent weights
__device__ float g_hT[2 * HD * BD];              // ping-pong hidden state, [j][b]
__device__ unsigned int g_bar[LD];               // per-layer grid barrier counters

// ---------------- helpers --------------------------------------------------
__device__ __forceinline__ void cp16(float* dst, const float* src) {
    unsigned s = (unsigned)__cvta_generic_to_shared(dst);
    asm volatile("cp.async.cg.shared.global [%0], [%1], 16;\n" :: "r"(s), "l"(src) : "memory");
}
__device__ __forceinline__ unsigned f2tf(float x) {
    unsigned r; asm("cvt.rna.tf32.f32 %0, %1;\n" : "=r"(r) : "f"(x)); return r;
}
__device__ __forceinline__ void tf_split(float x, float& hi, float& lo) {
    unsigned h = f2tf(x);
    hi = __uint_as_float(h);
    lo = __uint_as_float(f2tf(x - hi));
}
__device__ __forceinline__ void mma_tf32(float* d, const unsigned* a, const unsigned* b) {
    asm volatile(
        "mma.sync.aligned.m16n8k8.row.col.f32.tf32.tf32.f32 "
        "{%0,%1,%2,%3}, {%4,%5,%6,%7}, {%8,%9}, {%0,%1,%2,%3};\n"
        : "+f"(d[0]), "+f"(d[1]), "+f"(d[2]), "+f"(d[3])
        : "r"(a[0]), "r"(a[1]), "r"(a[2]), "r"(a[3]), "r"(b[0]), "r"(b[1]));
}

// ---------------- transpose rec_kernels: [L][512][1536] -> [L][1536][512] --
__global__ void k_trans(const float* __restrict__ in, float* __restrict__ out) {
    __shared__ float s[32][33];
    const int l  = blockIdx.z;
    const int n0 = blockIdx.x * 32;
    const int k0 = blockIdx.y * 32;
    const float* inl  = in  + (size_t)l * HD * G3;
    float*       outl = out + (size_t)l * G3 * HD;
    for (int r = threadIdx.y; r < 32; r += 8)
        s[r][threadIdx.x] = inl[(size_t)(k0 + r) * G3 + n0 + threadIdx.x];
    __syncthreads();
    for (int r = threadIdx.y; r < 32; r += 8)
        outl[(size_t)(n0 + r) * HD + k0 + threadIdx.x] = s[threadIdx.x][r];
}

// zero h0 and the per-layer barrier counters (no separate reset launches ->
// launch sequence stays aligned for ncu -s 5)
__global__ void k_zero(float* p, int n) {
    int i = blockIdx.x * blockDim.x + threadIdx.x;
    if (i < n) p[i] = 0.0f;
    if (i < LD) g_bar[i] = 0u;
}

// final state: d_out tail [b][j] from hT [j][b]
__global__ void k_final(const float* __restrict__ hT0, float* __restrict__ out) {
    int idx = blockIdx.x * blockDim.x + threadIdx.x;  // 65536
    int b = idx >> 9, j = idx & 511;
    out[idx] = hT0[(size_t)j * BD + b];
}

// ---------------- 3xTF32 tensor-core input GEMM ----------------------------
// C[M,1536] = A[M,512] @ Bw[512,1536] + bias, fp32-accurate via hi/lo split.
// CTA tile 128x128, kTile 16, 8 warps (each 64x32), double-buffered smem.
#define GP 132                       // padded smem row stride (floats)
#define GEMM_SMEM (4 * 2 * 16 * GP * 4)   // Ah,Al,Bh,Bl x 2 stages

__global__ __launch_bounds__(256, 1)
void k_gemm_tc(const float* __restrict__ A, const float* __restrict__ Bw,
               const float* __restrict__ bias, float* __restrict__ C) {
    extern __shared__ float sm[];
    float* Ah = sm;
    float* Al = Ah + 2 * 16 * GP;
    float* Bh = Al + 2 * 16 * GP;
    float* Bl = Bh + 2 * 16 * GP;

    const int tid  = threadIdx.x;
    const int lane = tid & 31;
    const int warp = tid >> 5;
    const int wm   = warp & 1;       // 2 warps along M (64 each)
    const int wn   = warp >> 1;      // 4 warps along N (32 each)
    const int n0   = blockIdx.x * 128;
    const int m0   = blockIdx.y * 128;

    // LDG indexing: A 512 float4 (row-major, 4 f4/row), B 512 float4
    const int a_row = tid >> 2, a_kq = tid & 3;
    const int b_k   = tid >> 5, b_nq = tid & 31;   // second B tile: b_k + 8

    float acc[4][4][4];
#pragma unroll
    for (int i = 0; i < 4; i++)
#pragma unroll
        for (int j = 0; j < 4; j++)
#pragma unroll
            for (int q = 0; q < 4; q++) acc[i][j][q] = 0.0f;

    float4 av0, av1, bv0, bv1;

    // prologue: load k-tile 0
    {
        const int k0 = 0;
        av0 = *(const float4*)(A + (size_t)(m0 + a_row) * HD + k0 + a_kq * 4);
        av1 = *(const float4*)(A + (size_t)(m0 + a_row + 64) * HD + k0 + a_kq * 4);
        bv0 = *(const float4*)(Bw + (size_t)(k0 + b_k) * G3 + n0 + b_nq * 4);
        bv1 = *(const float4*)(Bw + (size_t)(k0 + b_k + 8) * G3 + n0 + b_nq * 4);
    }

    for (int kt = 0; kt < 32; kt++) {
        const int st = kt & 1;
        // STS current tile into stage st
        {
            float* ah = Ah + st * 16 * GP;
            float* al = Al + st * 16 * GP;
            float f0[4] = {av0.x, av0.y, av0.z, av0.w};
            float f1[4] = {av1.x, av1.y, av1.z, av1.w};
#pragma unroll
            for (int j = 0; j < 4; j++) {
                float h, l;
                tf_split(f0[j], h, l);
                ah[(a_kq * 4 + j) * GP + a_row] = h;
                al[(a_kq * 4 + j) * GP + a_row] = l;
                tf_split(f1[j], h, l);
                ah[(a_kq * 4 + j) * GP + a_row + 64] = h;
                al[(a_kq * 4 + j) * GP + a_row + 64] = l;
            }
            float* bh = Bh + st * 16 * GP;
            float* bl = Bl + st * 16 * GP;
            float4 hv, lv;
            tf_split(bv0.x, hv.x, lv.x); tf_split(bv0.y, hv.y, lv.y);
            tf_split(bv0.z, hv.z, lv.z); tf_split(bv0.w, hv.w, lv.w);
            *(float4*)(bh + b_k * GP + b_nq * 4) = hv;
            *(float4*)(bl + b_k * GP + b_nq * 4) = lv;
            tf_split(bv1.x, hv.x, lv.x); tf_split(bv1.y, hv.y, lv.y);
            tf_split(bv1.z, hv.z, lv.z); tf_split(bv1.w, hv.w, lv.w);
            *(float4*)(bh + (b_k + 8) * GP + b_nq * 4) = hv;
            *(float4*)(bl + (b_k + 8) * GP + b_nq * 4) = lv;
        }
        __syncthreads();

        // prefetch next tile while computing
        if (kt < 31) {
            const int k0 = (kt + 1) * 16;
            av0 = *(const float4*)(A + (size_t)(m0 + a_row) * HD + k0 + a_kq * 4);
            av1 = *(const float4*)(A + (size_t)(m0 + a_row + 64) * HD + k0 + a_kq * 4);
            bv0 = *(const float4*)(Bw + (size_t)(k0 + b_k) * G3 + n0 + b_nq * 4);
            bv1 = *(const float4*)(Bw + (size_t)(k0 + b_k + 8) * G3 + n0 + b_nq * 4);
        }

        // compute on stage st
        {
            const float* ah = Ah + st * 16 * GP;
            const float* al = Al + st * 16 * GP;
            const float* bh = Bh + st * 16 * GP;
            const float* bl = Bl + st * 16 * GP;
            const int r0 = lane >> 2, c0 = lane & 3;
#pragma unroll
            for (int kk = 0; kk < 16; kk += 8) {
                unsigned a_h[4][4], a_l[4][4], b_h[4][2], b_l[4][2];
#pragma unroll
                for (int mt = 0; mt < 4; mt++) {
                    const int mb = wm * 64 + mt * 16 + r0;
                    a_h[mt][0] = __float_as_uint(ah[(kk + c0) * GP + mb]);
                    a_h[mt][1] = __float_as_uint(ah[(kk + c0) * GP + mb + 8]);
                    a_h[mt][2] = __float_as_uint(ah[(kk + c0 + 4) * GP + mb]);
                    a_h[mt][3] = __float_as_uint(ah[(kk + c0 + 4) * GP + mb + 8]);
                    a_l[mt][0] = __float_as_uint(al[(kk + c0) * GP + mb]);
                    a_l[mt][1] = __float_as_uint(al[(kk + c0) * GP + mb + 8]);
                    a_l[mt][2] = __float_as_uint(al[(kk + c0 + 4) * GP + mb]);
                    a_l[mt][3] = __float_as_uint(al[(kk + c0 + 4) * GP + mb + 8]);
                }
#pragma unroll
                for (int nt = 0; nt < 4; nt++) {
                    const int nb = wn * 32 + nt * 8 + r0;
                    b_h[nt][0] = __float_as_uint(bh[(kk + c0) * GP + nb]);
                    b_h[nt][1] = __float_as_uint(bh[(kk + c0 + 4) * GP + nb]);
                    b_l[nt][0] = __float_as_uint(bl[(kk + c0) * GP + nb]);
                    b_l[nt][1] = __float_as_uint(bl[(kk + c0 + 4) * GP + nb]);
                }
#pragma unroll
                for (int mt = 0; mt < 4; mt++)
#pragma unroll
                    for (int nt = 0; nt < 4; nt++) {
                        mma_tf32(acc[mt][nt], a_h[mt], b_h[nt]);
                        mma_tf32(acc[mt][nt], a_h[mt], b_l[nt]);
                        mma_tf32(acc[mt][nt], a_l[mt], b_h[nt]);
                    }
            }
        }
        if (kt < 31) __syncthreads();
    }

    // epilogue: bias add + STG.64
    const int r0 = lane >> 2, c2 = (lane & 3) * 2;
#pragma unroll
    for (int nt = 0; nt < 4; nt++) {
        const int col = n0 + wn * 32 + nt * 8 + c2;
        const float bz0 = bias[col], bz1 = bias[col + 1];
#pragma unroll
        for (int mt = 0; mt < 4; mt++) {
            const int m = m0 + wm * 64 + mt * 16 + r0;
            float2 v0 = {acc[mt][nt][0] + bz0, acc[mt][nt][1] + bz1};
            float2 v1 = {acc[mt][nt][2] + bz0, acc[mt][nt][3] + bz1};
            *(float2*)(C + (size_t)m * G3 + col)       = v0;
            *(float2*)(C + (size_t)(m + 8) * G3 + col) = v1;
        }
    }
}

// ---------------- persistent recurrent scan --------------------------------
// grid 128 = 2 b-tiles x 64 j-blocks (8 j each). 128 threads.
// Thread: 4 b's x 1 j x 3 gates (12 accumulators). One grid barrier per step.
#define SCAN_THREADS 128
#define WS_STRIDE 516
#define SCAN_SMEM ((24 * WS_STRIDE + 512 * 64) * 4)

__global__ __launch_bounds__(SCAN_THREADS, 1)
void k_scan(const float* __restrict__ XP, const float* __restrict__ WuT,
            const float* __restrict__ br, float* __restrict__ seq,
            float* __restrict__ hT0, float* __restrict__ hT1,
            unsigned int* __restrict__ bar) {
    extern __shared__ float sm[];
    float* Ws = sm;                       // [24][516]
    float* hs = sm + 24 * WS_STRIDE;      // [512][64]  (k-major, b fast)
    const int tid  = threadIdx.x;
    const int bt   = blockIdx.x & 1;      // b-tile (0/1 -> 64 b's)
    const int jblk = blockIdx.x >> 1;     // 0..63
    const int j0   = jblk * 8;
    const int tb   = tid & 15;
    const int tj   = tid >> 4;            // 0..7
    const int bloc = tb * 4;              // local b within 64
    const int b0   = bt * 64 + bloc;
    const int j    = j0 + tj;

    // stage Wu^T rows (z,r,h for this CTA's 8 j's) once for all 256 steps
    for (int r = 0; r < 24; r++) {
        const int g = r >> 3, jj = r & 7;
        const float4* src = (const float4*)(WuT + (size_t)(g * HD + j0 + jj) * HD);
        ((float4*)(Ws + r * WS_STRIDE))[tid] = src[tid];
    }
    __syncthreads();

    const float brz = br[j], brr = br[HD + j], brh = br[2 * HD + j];
    const float* w0 = Ws + (0 * 8 + tj) * WS_STRIDE;
    const float* w1 = Ws + (1 * 8 + tj) * WS_STRIDE;
    const float* w2 = Ws + (2 * 8 + tj) * WS_STRIDE;

    unsigned int bar_target = 0;
    for (int t = 0; t < TD; t++) {
        const float* hcur = (t & 1) ? hT1 : hT0;
        float*       hnxt = (t & 1) ? hT0 : hT1;

        // issue 4 k-chunks of h into smem via cp.async
#pragma unroll
        for (int c = 0; c < 4; c++) {
            const float* src = hcur + (size_t)(c * 128) * BD + bt * 64;
#pragma unroll
            for (int i = 0; i < 16; i++) {
                int idx = tid + i * 128;             // 0..2047 float4s
                int k = idx >> 4, f = idx & 15;
                cp16(hs + (size_t)(c * 128 + k) * 64 + f * 4,
                     src + (size_t)k * BD + f * 4);
            }
            asm volatile("cp.async.commit_group;\n" ::: "memory");
        }

        float acc[4][3];
#pragma unroll
        for (int i = 0; i < 4; i++) { acc[i][0] = 0.f; acc[i][1] = 0.f; acc[i][2] = 0.f; }

#pragma unroll
        for (int c = 0; c < 4; c++) {
            if (c == 0)      asm volatile("cp.async.wait_group 3;\n" ::: "memory");
            else if (c == 1) asm volatile("cp.async.wait_group 2;\n" ::: "memory");
            else if (c == 2) asm volatile("cp.async.wait_group 1;\n" ::: "memory");
            else             asm volatile("cp.async.wait_group 0;\n" ::: "memory");
            __syncthreads();
            const float* hc = hs + (size_t)c * 128 * 64 + bloc;
            const float* wz = w0 + c * 128;
            const float* wr = w1 + c * 128;
            const float* wh = w2 + c * 128;
#pragma unroll 8
            for (int k = 0; k < 128; k++) {
                float4 hv = *(const float4*)(hc + (size_t)k * 64);
                float a = wz[k], b = wr[k], cc = wh[k];
                acc[0][0] += hv.x * a;  acc[1][0] += hv.y * a;
                acc[2][0] += hv.z * a;  acc[3][0] += hv.w * a;
                acc[0][1] += hv.x * b;  acc[1][1] += hv.y * b;
                acc[2][1] += hv.z * b;  acc[3][1] += hv.w * b;
                acc[0][2] += hv.x * cc; acc[1][2] += hv.y * cc;
                acc[2][2] += hv.z * cc; acc[3][2] += hv.w * cc;
            }
        }

        // gate math + state update (h_old comes straight from smem)
#pragma unroll
        for (int i = 0; i < 4; i++) {
            const int b = b0 + i;
            const float* xprow = XP + ((size_t)b * TD + t) * G3;
            float xz = xprow[j], xr = xprow[HD + j], xh = xprow[2 * HD + j];
            float rz = acc[i][0] + brz;
            float rr = acc[i][1] + brr;
            float rh = acc[i][2] + brh;
            float z  = 1.0f / (1.0f + expf(-(xz + rz)));
            float r  = 1.0f / (1.0f + expf(-(xr + rr)));
            float hh = tanhf(xh + r * rh);
            float ho = hs[(size_t)j * 64 + bloc + i];
            float hn = z * ho + (1.0f - z) * hh;
            hnxt[(size_t)j * BD + b] = hn;
            seq[((size_t)b * TD + t) * HD + j] = hn;
        }

        // grid barrier
        bar_target += gridDim.x;
        __syncthreads();
        if (tid == 0) {
            __threadfence();
            atomicAdd(bar, 1u);
            while (atomicAdd(bar, 0u) < bar_target) { }
            __threadfence();
        }
        __syncthreads();
    }
}

// ---------------- launch ---------------------------------------------------
extern "C" void kernel_launch(void* const* d_in, const int* in_sizes, int n_in,
                              void* d_out, int out_size) {
    const float* x      = (const float*)d_in[0];  // [128,256,512]
    const float* kern   = (const float*)d_in[1];  // [3,512,1536]
    const float* rkern  = (const float*)d_in[2];  // [3,512,1536]
    const float* biases = (const float*)d_in[3];  // [3,2,1536]
    float* out = (float*)d_out;

    cudaFuncSetAttribute(k_scan, cudaFuncAttributeMaxDynamicSharedMemorySize, SCAN_SMEM);
    cudaFuncSetAttribute(k_gemm_tc, cudaFuncAttributeMaxDynamicSharedMemorySize, GEMM_SMEM);

    float *XP, *X1, *X2, *WuT, *hT;
    unsigned int* bar;
    cudaGetSymbolAddress((void**)&XP,  g_XP);
    cudaGetSymbolAddress((void**)&X1,  g_X1);
    cudaGetSymbolAddress((void**)&X2,  g_X2);
    cudaGetSymbolAddress((void**)&WuT, g_WuT);
    cudaGetSymbolAddress((void**)&hT,  g_hT);
    cudaGetSymbolAddress((void**)&bar, g_bar);
    float* hT0 = hT;
    float* hT1 = hT + HD * BD;

    k_trans<<<dim3(G3 / 32, HD / 32, LD), dim3(32, 8)>>>(rkern, WuT);
    k_zero<<<(HD * BD + 255) / 256, 256>>>(hT0, HD * BD);

    const float* cur = x;
    float* outs[3] = {X1, X2, out};
    for (int l = 0; l < LD; l++) {
        const float* Wk = kern + (size_t)l * HD * G3;
        const float* b0 = biases + (size_t)l * 2 * G3;
        k_gemm_tc<<<dim3(G3 / 128, MD / 128), 256, GEMM_SMEM>>>(cur, Wk, b0, XP);
        k_scan<<<128, SCAN_THREADS, SCAN_SMEM>>>(
            XP, WuT + (size_t)l * G3 * HD, b0 + G3, outs[l], hT0, hT1, bar + l);
        cur = outs[l];
    }
    k_final<<<(HD * BD + 511) / 512, 512>>>(hT0, out + (size_t)MD * HD);
}